// round 14
// baseline (speedup 1.0000x reference)
#include <cuda_runtime.h>
#include <cuda_fp16.h>
#include <cstdint>

#define BS 8
#define SEQ 16
#define HW 1024
#define CK 256
#define CV 3
#define NSTEP 15

#define KTOT 256
#define KC 64
#define NCHUNKS (KTOT / KC) // 4
#define TM 128
#define TN 128
#define STEP_GEMM 1024
#define STEP_CHAIN 256
#define PAIR (STEP_GEMM + STEP_CHAIN)   // 1280
#define GRID (NSTEP * PAIR)             // 19200
#define GSMEM 65536

// ---------------- persistent scratch ----------------------------------------
__device__ __align__(256) __half g_k2[(size_t)BS * SEQ * HW * KTOT];
__device__ __align__(256) __half g_m2[(size_t)BS * NSTEP * HW * KTOT];
__device__ __align__(256) __half g_S[(size_t)2 * BS * NSTEP * HW * HW];  // logit - tilemax
__device__ __align__(256) float g_stats[(size_t)2 * BS * NSTEP * HW * 16]; // 64-col tile maxes
__device__ float g_sig[BS * SEQ * HW];
__device__ __align__(256) float g_mv[2][BS * HW * 4];
__device__ __align__(256) float g_pv[2][BS * HW * 4];
__device__ int g_mask[BS * SEQ];
__device__ int g_gemm_done[NSTEP];
__device__ int g_chain_done[NSTEP];

// ---------------- PTX helpers ------------------------------------------------
__device__ __forceinline__ uint32_t s2u(const void* p) {
    uint32_t a;
    asm("{ .reg .u64 t; cvta.to.shared.u64 t, %1; cvt.u32.u64 %0, t; }"
        : "=r"(a) : "l"(p));
    return a;
}
#define SWZ(o) ((o) ^ (((o) >> 3) & 0x70))

__device__ __forceinline__ void cp16(uint32_t dst, const void* src) {
    asm volatile("cp.async.cg.shared.global [%0], [%1], 16;" ::"r"(dst), "l"(src));
}
#define CP_COMMIT() asm volatile("cp.async.commit_group;")

__device__ __forceinline__ void ldsm4(uint32_t& r0, uint32_t& r1, uint32_t& r2,
                                      uint32_t& r3, uint32_t addr) {
    asm volatile("ldmatrix.sync.aligned.m8n8.x4.shared.b16 {%0,%1,%2,%3}, [%4];"
                 : "=r"(r0), "=r"(r1), "=r"(r2), "=r"(r3) : "r"(addr));
}
__device__ __forceinline__ void mma16816(float* d, const uint32_t* a,
                                         const uint32_t* b) {
    asm volatile(
        "mma.sync.aligned.m16n8k16.row.col.f32.f16.f16.f32 "
        "{%0,%1,%2,%3}, {%4,%5,%6,%7}, {%8,%9}, {%0,%1,%2,%3};"
        : "+f"(d[0]), "+f"(d[1]), "+f"(d[2]), "+f"(d[3])
        : "r"(a[0]), "r"(a[1]), "r"(a[2]), "r"(a[3]), "r"(b[0]), "r"(b[1]));
}
__device__ __forceinline__ int ld_acq(const int* p) {
    int v;
    asm volatile("ld.acquire.gpu.b32 %0, [%1];" : "=r"(v) : "l"(p) : "memory");
    return v;
}
__device__ __forceinline__ uint32_t pack_h2(float a, float b) {
    __half2 h = __floats2half2_rn(a, b);
    return *(uint32_t*)&h;
}

// ---------------- small kernels ----------------------------------------------
__global__ void mask_decode_kernel(const unsigned char* __restrict__ m) {
    __shared__ int not_i32;
    int t = threadIdx.x;  // 128
    if (t == 0) not_i32 = 0;
    __syncthreads();
    if (t < 32) {
        int w = ((const int*)m)[t];
        if (w != 0 && w != 1) not_i32 = 1;
    }
    __syncthreads();
    g_mask[t] = (!not_i32) ? (((const int*)m)[t] != 0) : (m[t] != 0);
}

__global__ void sig_kernel(const float* __restrict__ att) {
    int e = blockIdx.x * 256 + threadIdx.x;  // 131072
    g_sig[e] = 1.f / (1.f + __expf(-att[e]));
}

__global__ void prep_kernel(const float* __restrict__ k) {
    int t = blockIdx.x * 256 + threadIdx.x;  // 524288
    int cg = t & 63, p = (t >> 6) & 1023, b = t >> 16;
    float4 m = make_float4(0.f, 0.f, 0.f, 0.f);
#pragma unroll 1
    for (int s = 0; s < SEQ; s++) {
        float4 kv = *(const float4*)(k + ((size_t)(b * SEQ + s) * HW + p) * CK + cg * 4);
        {
            uint2 pk = {pack_h2(kv.x, kv.y), pack_h2(kv.z, kv.w)};
            *(uint2*)(g_k2 + ((size_t)(b * SEQ + s) * HW + p) * KTOT + cg * 4) = pk;
        }
        if (s < NSTEP) {
            float g = g_sig[(b * SEQ + s) * HW + p];
            m.x = g * kv.x + (1.f - g) * m.x;
            m.y = g * kv.y + (1.f - g) * m.y;
            m.z = g * kv.z + (1.f - g) * m.z;
            m.w = g * kv.w + (1.f - g) * m.w;
            uint2 pk = {pack_h2(m.x, m.y), pack_h2(m.z, m.w)};
            *(uint2*)(g_m2 + ((size_t)(b * NSTEP + s) * HW + p) * KTOT + cg * 4) = pk;
        }
    }
}

__global__ void init_kernel(const float* __restrict__ v) {
    int t = blockIdx.x * 256 + threadIdx.x;  // 8192
    int b = t >> 10, p = t & 1023;
    if (t < 2 * NSTEP) {
        if (t < NSTEP) g_gemm_done[t] = 0;
        else g_chain_done[t - NSTEP] = 0;
    }
    ((float4*)g_mv[0])[t] = make_float4(0.f, 0.f, 0.f, 0.f);
    const float* vp = v + ((size_t)(b * SEQ) * HW + p) * CV;
    ((float4*)g_pv[0])[t] = make_float4(vp[0], vp[1], vp[2], 0.f);
}

__global__ void gt_copy_kernel(const float* __restrict__ v, float* __restrict__ gt) {
    int e = blockIdx.x * blockDim.x + threadIdx.x;  // 92160 float4
    int b = e / (NSTEP * HW * CV / 4);
    int r = e - b * (NSTEP * HW * CV / 4);
    const float4* src = (const float4*)(v + ((size_t)b * SEQ + 1) * HW * CV);
    float4* dst = (float4*)(gt + (size_t)b * NSTEP * HW * CV);
    dst[r] = src[r];
}

// ---------------- mega kernel: GEMM + chain, delayed chain schedule ----------
__global__ __launch_bounds__(256, 2) void mega_kernel(
    const float* __restrict__ vin, float* __restrict__ out_v) {
    extern __shared__ char smem[];
    int r = blockIdx.x;
    int t = threadIdx.x, w = t >> 5, l = t & 31;

    int step, sub;
    bool is_gemm;
    if (r < 2 * STEP_GEMM) {
        is_gemm = true; step = r >> 10; sub = r & 1023;
    } else if (r < 2 * STEP_GEMM + 13 * PAIR) {
        int r2 = r - 2 * STEP_GEMM;
        int pp = r2 / PAIR, q = r2 - pp * PAIR;
        if (q < STEP_CHAIN) { is_gemm = false; step = pp; sub = q; }
        else { is_gemm = true; step = pp + 2; sub = q - STEP_CHAIN; }
    } else {
        int r3 = r - (2 * STEP_GEMM + 13 * PAIR);
        is_gemm = false; step = 13 + (r3 >> 8); sub = r3 & 255;
    }

    if (is_gemm) {
        // ================= GEMM tile =================
        uint32_t sb = s2u(smem);
        int warp_m = w & 3, warp_n = w >> 2;
        int pass = sub >> 9, b = (sub >> 6) & 7, qt = (sub >> 3) & 7, nt = sub & 7;
        int i = step;
        int ctx = (pass * BS + b) * NSTEP + i;

        const __half* A = g_k2 + ((size_t)((b * SEQ + i + 1) * HW) + qt * TM) * KTOT;
        const __half* B =
            pass ? g_m2 + ((size_t)((b * NSTEP + i) * HW) + nt * TN) * KTOT
                 : g_k2 + ((size_t)((b * SEQ + i) * HW) + nt * TN) * KTOT;

        auto load_chunk = [&](int ch, int buf) {
            uint32_t abase = sb + buf * 32768;
            uint32_t bbase = abase + 16384;
#pragma unroll
            for (int j = 0; j < 4; j++) {
                int idx = j * 256 + t;
                int row = idx >> 3, k8 = idx & 7;
                uint32_t off = SWZ((uint32_t)(row * 128 + k8 * 16));
                cp16(abase + off, A + (size_t)row * KTOT + ch * KC + k8 * 8);
                cp16(bbase + off, B + (size_t)row * KTOT + ch * KC + k8 * 8);
            }
            CP_COMMIT();
        };

        float acc[2][8][4];
#pragma unroll
        for (int mt = 0; mt < 2; mt++)
#pragma unroll
            for (int n8 = 0; n8 < 8; n8++)
#pragma unroll
                for (int u = 0; u < 4; u++) acc[mt][n8][u] = 0.f;

        load_chunk(0, 0);
        load_chunk(1, 1);

#pragma unroll 1
        for (int c = 0; c < NCHUNKS; c++) {
            if (c < NCHUNKS - 1)
                asm volatile("cp.async.wait_group 1;");
            else
                asm volatile("cp.async.wait_group 0;");
            __syncthreads();

            uint32_t abase = sb + (c & 1) * 32768;
            uint32_t bbase = abase + 16384;
#pragma unroll
            for (int ks = 0; ks < 4; ks++) {
                uint32_t a[2][4];
#pragma unroll
                for (int mt = 0; mt < 2; mt++) {
                    int row = warp_m * 32 + mt * 16 + (l & 15);
                    int kb = ks * 32 + (l >> 4) * 16;
                    ldsm4(a[mt][0], a[mt][1], a[mt][2], a[mt][3],
                          abase + SWZ((uint32_t)(row * 128 + kb)));
                }
                uint32_t bf[4][4];
#pragma unroll
                for (int g16 = 0; g16 < 4; g16++) {
                    int n = warp_n * 64 + g16 * 16 + (l >> 4) * 8 + (l & 7);
                    int kb = ks * 32 + ((l >> 3) & 1) * 16;
                    ldsm4(bf[g16][0], bf[g16][1], bf[g16][2], bf[g16][3],
                          bbase + SWZ((uint32_t)(n * 128 + kb)));
                }
#pragma unroll
                for (int mt = 0; mt < 2; mt++)
#pragma unroll
                    for (int n8 = 0; n8 < 8; n8++) {
                        uint32_t bp[2] = {bf[n8 >> 1][(n8 & 1) * 2],
                                          bf[n8 >> 1][(n8 & 1) * 2 + 1]};
                        mma16816(acc[mt][n8], a[mt], bp);
                    }
            }
            __syncthreads();
            if (c + 2 < NCHUNKS) load_chunk(c + 2, c & 1);
        }

        // ---- epilogue: tile-max-relative fp16 logits (exp-free flash) ----
        __half* So = g_S + ((size_t)ctx << 20) +
                     (size_t)(qt * TM) * HW + nt * TN;
        int j = l & 3, q = l >> 2;
#pragma unroll
        for (int mt = 0; mt < 2; mt++) {
            // per-row max over this warp's 64-col tile (quad-local: no barriers)
            float mx0 = -1e30f, mx1 = -1e30f;
#pragma unroll
            for (int n8 = 0; n8 < 8; n8++) {
                mx0 = fmaxf(mx0, fmaxf(acc[mt][n8][0], acc[mt][n8][1]));
                mx1 = fmaxf(mx1, fmaxf(acc[mt][n8][2], acc[mt][n8][3]));
            }
            mx0 = fmaxf(mx0, __shfl_xor_sync(0xffffffffu, mx0, 1));
            mx0 = fmaxf(mx0, __shfl_xor_sync(0xffffffffu, mx0, 2));
            mx1 = fmaxf(mx1, __shfl_xor_sync(0xffffffffu, mx1, 1));
            mx1 = fmaxf(mx1, __shfl_xor_sync(0xffffffffu, mx1, 2));
            int r0 = warp_m * 32 + mt * 16 + q;
            if (j == 0) {
                int st = nt * 2 + warp_n;
                g_stats[(((size_t)ctx << 10) + qt * TM + r0) * 16 + st] = mx0;
                g_stats[(((size_t)ctx << 10) + qt * TM + r0 + 8) * 16 + st] = mx1;
            }
#pragma unroll
            for (int p = 0; p < 4; p++) {
                int n8a = 2 * p, n8b = 2 * p + 1;
                uint32_t v0 = pack_h2(acc[mt][n8a][0] - mx0, acc[mt][n8a][1] - mx0);
                uint32_t v1 = pack_h2(acc[mt][n8b][0] - mx0, acc[mt][n8b][1] - mx0);
                uint32_t v2 = pack_h2(acc[mt][n8a][2] - mx1, acc[mt][n8a][3] - mx1);
                uint32_t v3 = pack_h2(acc[mt][n8b][2] - mx1, acc[mt][n8b][3] - mx1);
                // 4x4 xor transpose within quad
#pragma unroll
                for (int d = 1; d < 4; d++) {
                    int idx = j ^ d;
                    uint32_t tmp = (idx == 0) ? v0 : (idx == 1) ? v1
                                 : (idx == 2) ? v2 : v3;
                    tmp = __shfl_xor_sync(0xffffffffu, tmp, d);
                    if (idx == 0) v0 = tmp;
                    else if (idx == 1) v1 = tmp;
                    else if (idx == 2) v2 = tmp;
                    else v3 = tmp;
                }
                int row = warp_m * 32 + mt * 16 + q + (j >> 1) * 8;
                int col = warp_n * 64 + p * 16 + (j & 1) * 8;
                *(uint4*)(So + (size_t)row * HW + col) = make_uint4(v0, v1, v2, v3);
            }
        }
        __threadfence();
        __syncthreads();
        if (t == 0) atomicAdd(&g_gemm_done[step], 1);
    } else {
        // ================= chain block =================
        int b = sub >> 5, rg = sub & 31;
        int i = step, cur = step & 1;

        if (t == 0) {
            while (ld_acq(&g_gemm_done[i]) < STEP_GEMM) __nanosleep(128);
            if (i > 0)
                while (ld_acq(&g_chain_done[i - 1]) < STEP_CHAIN) __nanosleep(128);
        }
        __syncthreads();

        float4* Vp = (float4*)smem;        // [1024]
        float4* Vm = Vp + HW;              // [1024]
#pragma unroll
        for (int jj = 0; jj < 4; jj++) {
            int p = jj * 256 + t;
            float4 pv = ((const float4*)g_pv[cur])[b * HW + p];
            float4 mo = ((const float4*)g_mv[cur])[b * HW + p];
            float g = g_sig[(b * SEQ + i) * HW + p];
            float4 mn;
            mn.x = g * pv.x + (1.f - g) * mo.x;
            mn.y = g * pv.y + (1.f - g) * mo.y;
            mn.z = g * pv.z + (1.f - g) * mo.z;
            mn.w = 0.f;
            Vp[p] = pv;
            Vm[p] = mn;
            if (rg == 0) ((float4*)g_mv[cur ^ 1])[b * HW + p] = mn;
        }
        __syncthreads();

        float recs[4][3];
#pragma unroll 1
        for (int pass = 0; pass < 2; pass++) {
            int ctx = (pass * BS + b) * NSTEP + i;
            const __half* Sb = g_S + ((size_t)ctx << 20);
            const float4* Vs = pass ? Vm : Vp;
            float wgt = pass ? 0.1f : 0.9f;
#pragma unroll 1
            for (int rr = 0; rr < 4; rr++) {
                int q = rg * 32 + w * 4 + rr;
                // merge 64-col tile maxes -> global max; build offsets
                const float* St = g_stats + (((size_t)ctx << 10) + q) * 16;
                float off[16];
                float M = -1e30f;
#pragma unroll
                for (int tt = 0; tt < 16; tt++) {
                    off[tt] = St[tt];
                    M = fmaxf(M, off[tt]);
                }
#pragma unroll
                for (int tt = 0; tt < 16; tt++) off[tt] -= M;

                const __half* Srow = Sb + (size_t)q * HW;
                float s = 0.f, d0 = 0.f, d1 = 0.f, d2 = 0.f;
#pragma unroll
                for (int j = 0; j < 32; j++) {
                    float e = __expf(__half2float(Srow[j * 32 + l]) + off[j >> 1]);
                    float4 vv = Vs[j * 32 + l];
                    s += e;
                    d0 += e * vv.x; d1 += e * vv.y; d2 += e * vv.z;
                }
#pragma unroll
                for (int o = 16; o > 0; o >>= 1) {
                    s += __shfl_xor_sync(0xffffffffu, s, o);
                    d0 += __shfl_xor_sync(0xffffffffu, d0, o);
                    d1 += __shfl_xor_sync(0xffffffffu, d1, o);
                    d2 += __shfl_xor_sync(0xffffffffu, d2, o);
                }
                float inv = wgt / s;
                if (pass == 0) {
                    recs[rr][0] = d0 * inv; recs[rr][1] = d1 * inv; recs[rr][2] = d2 * inv;
                } else {
                    recs[rr][0] += d0 * inv; recs[rr][1] += d1 * inv; recs[rr][2] += d2 * inv;
                }
            }
        }

        if (l == 0) {
            bool mk = g_mask[b * SEQ + i] != 0;
            float* pvn = (float*)g_pv[cur ^ 1] + (size_t)b * HW * 4;
#pragma unroll
            for (int rr = 0; rr < 4; rr++) {
                int q = rg * 32 + w * 4 + rr;
                const float* vp = vin + ((size_t)(b * SEQ + i) * HW + q) * CV;
                float4 o;
                o.x = mk ? vp[0] : recs[rr][0];
                o.y = mk ? vp[1] : recs[rr][1];
                o.z = mk ? vp[2] : recs[rr][2];
                o.w = 0.f;
                ((float4*)pvn)[q] = o;
                float* op = out_v + ((size_t)(b * NSTEP + i) * HW + q) * CV;
                op[0] = recs[rr][0]; op[1] = recs[rr][1]; op[2] = recs[rr][2];
            }
        }
        __threadfence();
        __syncthreads();
        if (t == 0) atomicAdd(&g_chain_done[step], 1);
    }
}

// ---------------- host launcher ----------------------------------------------
extern "C" void kernel_launch(void* const* d_in, const int* in_sizes, int n_in,
                              void* d_out, int out_size) {
    const float* k = (const float*)d_in[0];
    const float* v = (const float*)d_in[1];
    const float* att = (const float*)d_in[2];
    const unsigned char* mask = (const unsigned char*)d_in[3];
    float* out_v = (float*)d_out;
    float* gt = out_v + (size_t)out_size / 2;

    cudaFuncSetAttribute(mega_kernel, cudaFuncAttributeMaxDynamicSharedMemorySize,
                         GSMEM);

    mask_decode_kernel<<<1, BS * SEQ>>>(mask);
    sig_kernel<<<BS * SEQ * HW / 256, 256>>>(att);
    prep_kernel<<<BS * HW * 64 / 256, 256>>>(k);
    init_kernel<<<BS * HW / 256, 256>>>(v);
    gt_copy_kernel<<<360, 256>>>(v, gt);

    mega_kernel<<<GRID, 256, GSMEM>>>(v, out_v);
}

// round 15
// speedup vs baseline: 1.2316x; 1.2316x over previous
#include <cuda_runtime.h>
#include <cuda_fp16.h>
#include <cstdint>

#define BS 8
#define SEQ 16
#define HW 1024
#define CK 256
#define CV 3
#define NSTEP 15

#define KTOT 256
#define KC 64
#define NCHUNKS (KTOT / KC) // 4
#define TM 128
#define TN 128
#define STEP_GEMM 1024
#define STEP_CHAIN 256
#define PAIR (STEP_GEMM + STEP_CHAIN)   // 1280
#define NGT 360
#define GRID (NSTEP * PAIR + NGT)       // 19560
#define GSMEM 65536

// ---------------- persistent scratch ----------------------------------------
__device__ __align__(256) __half g_k2[(size_t)BS * SEQ * HW * KTOT];
__device__ __align__(256) __half g_m2[(size_t)BS * NSTEP * HW * KTOT];
__device__ float g_S[(size_t)2 * BS * NSTEP * HW * HW];  // fp32 logits
__device__ float g_sig[BS * SEQ * HW];
__device__ __align__(256) float g_mv[2][BS * HW * 4];
__device__ __align__(256) float g_pv[2][BS * HW * 4];
__device__ int g_mask[BS * SEQ];
__device__ int g_gemm_done[NSTEP];
__device__ int g_chain_done[NSTEP];

// ---------------- PTX helpers ------------------------------------------------
__device__ __forceinline__ uint32_t s2u(const void* p) {
    uint32_t a;
    asm("{ .reg .u64 t; cvta.to.shared.u64 t, %1; cvt.u32.u64 %0, t; }"
        : "=r"(a) : "l"(p));
    return a;
}
#define SWZ(o) ((o) ^ (((o) >> 3) & 0x70))

__device__ __forceinline__ void cp16(uint32_t dst, const void* src) {
    asm volatile("cp.async.cg.shared.global [%0], [%1], 16;" ::"r"(dst), "l"(src));
}
#define CP_COMMIT() asm volatile("cp.async.commit_group;")

__device__ __forceinline__ void ldsm4(uint32_t& r0, uint32_t& r1, uint32_t& r2,
                                      uint32_t& r3, uint32_t addr) {
    asm volatile("ldmatrix.sync.aligned.m8n8.x4.shared.b16 {%0,%1,%2,%3}, [%4];"
                 : "=r"(r0), "=r"(r1), "=r"(r2), "=r"(r3) : "r"(addr));
}
__device__ __forceinline__ void mma16816(float* d, const uint32_t* a,
                                         const uint32_t* b) {
    asm volatile(
        "mma.sync.aligned.m16n8k16.row.col.f32.f16.f16.f32 "
        "{%0,%1,%2,%3}, {%4,%5,%6,%7}, {%8,%9}, {%0,%1,%2,%3};"
        : "+f"(d[0]), "+f"(d[1]), "+f"(d[2]), "+f"(d[3])
        : "r"(a[0]), "r"(a[1]), "r"(a[2]), "r"(a[3]), "r"(b[0]), "r"(b[1]));
}
__device__ __forceinline__ int ld_acq(const int* p) {
    int v;
    asm volatile("ld.acquire.gpu.b32 %0, [%1];" : "=r"(v) : "l"(p) : "memory");
    return v;
}
__device__ __forceinline__ uint32_t pack_h2(float a, float b) {
    __half2 h = __floats2half2_rn(a, b);
    return *(uint32_t*)&h;
}

// ---------------- init: counters + state + mask decode -----------------------
__global__ void init_kernel(const float* __restrict__ v,
                            const unsigned char* __restrict__ m) {
    __shared__ int not_i32;
    int tid = threadIdx.x;
    int t = blockIdx.x * 256 + tid;  // 8192
    if (tid == 0) not_i32 = 0;
    __syncthreads();
    if (blockIdx.x == 0 && tid < 32) {
        int wv = ((const int*)m)[tid];
        if (wv != 0 && wv != 1) not_i32 = 1;
    }
    __syncthreads();
    if (blockIdx.x == 0) {
        if (tid < 128)
            g_mask[tid] = (!not_i32) ? (((const int*)m)[tid] != 0) : (m[tid] != 0);
        if (tid >= 128 && tid < 128 + NSTEP) g_gemm_done[tid - 128] = 0;
        if (tid >= 160 && tid < 160 + NSTEP) g_chain_done[tid - 160] = 0;
    }
    int b = t >> 10, p = t & 1023;
    ((float4*)g_mv[0])[t] = make_float4(0.f, 0.f, 0.f, 0.f);
    const float* vp = v + ((size_t)(b * SEQ) * HW + p) * CV;
    ((float4*)g_pv[0])[t] = make_float4(vp[0], vp[1], vp[2], 0.f);
}

// fused: sigmoid inline + k -> fp16 + m_k recurrence -> fp16; k read once
__global__ void prep_kernel(const float* __restrict__ k,
                            const float* __restrict__ att) {
    int t = blockIdx.x * 256 + threadIdx.x;  // 524288
    int cg = t & 63, p = (t >> 6) & 1023, b = t >> 16;
    float4 m = make_float4(0.f, 0.f, 0.f, 0.f);
#pragma unroll 1
    for (int s = 0; s < SEQ; s++) {
        float4 kv = *(const float4*)(k + ((size_t)(b * SEQ + s) * HW + p) * CK + cg * 4);
        {
            uint2 pk = {pack_h2(kv.x, kv.y), pack_h2(kv.z, kv.w)};
            *(uint2*)(g_k2 + ((size_t)(b * SEQ + s) * HW + p) * KTOT + cg * 4) = pk;
        }
        if (s < NSTEP) {
            float g = 1.f / (1.f + __expf(-att[(b * SEQ + s) * HW + p]));
            if (cg == 0) g_sig[(b * SEQ + s) * HW + p] = g;
            m.x = g * kv.x + (1.f - g) * m.x;
            m.y = g * kv.y + (1.f - g) * m.y;
            m.z = g * kv.z + (1.f - g) * m.z;
            m.w = g * kv.w + (1.f - g) * m.w;
            uint2 pk = {pack_h2(m.x, m.y), pack_h2(m.z, m.w)};
            *(uint2*)(g_m2 + ((size_t)(b * NSTEP + s) * HW + p) * KTOT + cg * 4) = pk;
        }
    }
}

// ---------------- mega kernel: GEMM + chain (4:1 interleaved) + gt -----------
// bid order: [G0][G1][ G2 with C0 woven every 5th ][ G3 + C1 ]...[G14 + C12]
//            [C13][C14][gt]
__global__ __launch_bounds__(256, 2) void mega_kernel(
    const float* __restrict__ vin, float* __restrict__ out_v,
    float* __restrict__ gt) {
    extern __shared__ char smem[];
    int r = blockIdx.x;
    int t = threadIdx.x, w = t >> 5, l = t & 31;

    if (r >= NSTEP * PAIR) {
        // ---- gt copy (independent; dispatched last, fills the drain) ----
        int e = (r - NSTEP * PAIR) * 256 + t;  // 92160 float4
        int b = e / (NSTEP * HW * CV / 4);
        int rr = e - b * (NSTEP * HW * CV / 4);
        const float4* src = (const float4*)(vin + ((size_t)b * SEQ + 1) * HW * CV);
        float4* dst = (float4*)(gt + (size_t)b * NSTEP * HW * CV);
        dst[rr] = src[rr];
        return;
    }

    int step, sub;
    bool is_gemm;
    if (r < 2 * STEP_GEMM) {
        is_gemm = true; step = r >> 10; sub = r & 1023;
    } else if (r < 2 * STEP_GEMM + 13 * PAIR) {
        int r2 = r - 2 * STEP_GEMM;
        int wdw = r2 / PAIR, j = r2 - wdw * PAIR;
        if (j % 5 == 4) { is_gemm = false; step = wdw; sub = j / 5; }
        else           { is_gemm = true;  step = wdw + 2; sub = j - j / 5; }
    } else {
        int r3 = r - (2 * STEP_GEMM + 13 * PAIR);
        is_gemm = false; step = 13 + (r3 >> 8); sub = r3 & 255;
    }

    if (is_gemm) {
        // ================= GEMM tile =================
        uint32_t sb = s2u(smem);
        int warp_m = w & 3, warp_n = w >> 2;
        int pass = sub >> 9, b = (sub >> 6) & 7, qt = (sub >> 3) & 7, nt = sub & 7;
        int i = step;

        const __half* A = g_k2 + ((size_t)((b * SEQ + i + 1) * HW) + qt * TM) * KTOT;
        const __half* B =
            pass ? g_m2 + ((size_t)((b * NSTEP + i) * HW) + nt * TN) * KTOT
                 : g_k2 + ((size_t)((b * SEQ + i) * HW) + nt * TN) * KTOT;

        auto load_chunk = [&](int ch, int buf) {
            uint32_t abase = sb + buf * 32768;
            uint32_t bbase = abase + 16384;
#pragma unroll
            for (int j = 0; j < 4; j++) {
                int idx = j * 256 + t;
                int row = idx >> 3, k8 = idx & 7;
                uint32_t off = SWZ((uint32_t)(row * 128 + k8 * 16));
                cp16(abase + off, A + (size_t)row * KTOT + ch * KC + k8 * 8);
                cp16(bbase + off, B + (size_t)row * KTOT + ch * KC + k8 * 8);
            }
            CP_COMMIT();
        };

        float acc[2][8][4];
#pragma unroll
        for (int mt = 0; mt < 2; mt++)
#pragma unroll
            for (int n8 = 0; n8 < 8; n8++)
#pragma unroll
                for (int u = 0; u < 4; u++) acc[mt][n8][u] = 0.f;

        load_chunk(0, 0);
        load_chunk(1, 1);

#pragma unroll 1
        for (int c = 0; c < NCHUNKS; c++) {
            if (c < NCHUNKS - 1)
                asm volatile("cp.async.wait_group 1;");
            else
                asm volatile("cp.async.wait_group 0;");
            __syncthreads();

            uint32_t abase = sb + (c & 1) * 32768;
            uint32_t bbase = abase + 16384;
#pragma unroll
            for (int ks = 0; ks < 4; ks++) {
                uint32_t a[2][4];
#pragma unroll
                for (int mt = 0; mt < 2; mt++) {
                    int row = warp_m * 32 + mt * 16 + (l & 15);
                    int kb = ks * 32 + (l >> 4) * 16;
                    ldsm4(a[mt][0], a[mt][1], a[mt][2], a[mt][3],
                          abase + SWZ((uint32_t)(row * 128 + kb)));
                }
                uint32_t bf[4][4];
#pragma unroll
                for (int g16 = 0; g16 < 4; g16++) {
                    int n = warp_n * 64 + g16 * 16 + (l >> 4) * 8 + (l & 7);
                    int kb = ks * 32 + ((l >> 3) & 1) * 16;
                    ldsm4(bf[g16][0], bf[g16][1], bf[g16][2], bf[g16][3],
                          bbase + SWZ((uint32_t)(n * 128 + kb)));
                }
#pragma unroll
                for (int mt = 0; mt < 2; mt++)
#pragma unroll
                    for (int n8 = 0; n8 < 8; n8++) {
                        uint32_t bp[2] = {bf[n8 >> 1][(n8 & 1) * 2],
                                          bf[n8 >> 1][(n8 & 1) * 2 + 1]};
                        mma16816(acc[mt][n8], a[mt], bp);
                    }
            }
            __syncthreads();
            if (c + 2 < NCHUNKS) load_chunk(c + 2, c & 1);
        }

        float* So = g_S + (size_t)((pass * BS + b) * NSTEP + i) * HW * HW +
                    (size_t)(qt * TM) * HW + nt * TN;
#pragma unroll
        for (int mt = 0; mt < 2; mt++)
#pragma unroll
            for (int n8 = 0; n8 < 8; n8++) {
                int r0 = warp_m * 32 + mt * 16 + (l >> 2);
                int c0 = warp_n * 64 + n8 * 8 + (l & 3) * 2;
                *(float2*)(So + (size_t)r0 * HW + c0) =
                    make_float2(acc[mt][n8][0], acc[mt][n8][1]);
                *(float2*)(So + (size_t)(r0 + 8) * HW + c0) =
                    make_float2(acc[mt][n8][2], acc[mt][n8][3]);
            }
        __threadfence();
        __syncthreads();
        if (t == 0) atomicAdd(&g_gemm_done[step], 1);
    } else {
        // ================= chain block =================
        int b = sub >> 5, rg = sub & 31;
        int i = step, cur = step & 1;

        if (t == 0) {
            while (ld_acq(&g_gemm_done[i]) < STEP_GEMM) __nanosleep(128);
            if (i > 0)
                while (ld_acq(&g_chain_done[i - 1]) < STEP_CHAIN) __nanosleep(128);
        }
        __syncthreads();

        float4* Vp = (float4*)smem;        // [1024]
        float4* Vm = Vp + HW;              // [1024]
#pragma unroll
        for (int jj = 0; jj < 4; jj++) {
            int p = jj * 256 + t;
            float4 pv = ((const float4*)g_pv[cur])[b * HW + p];
            float4 mo = ((const float4*)g_mv[cur])[b * HW + p];
            float g = g_sig[(b * SEQ + i) * HW + p];
            float4 mn;
            mn.x = g * pv.x + (1.f - g) * mo.x;
            mn.y = g * pv.y + (1.f - g) * mo.y;
            mn.z = g * pv.z + (1.f - g) * mo.z;
            mn.w = 0.f;
            Vp[p] = pv;
            Vm[p] = mn;
            if (rg == 0) ((float4*)g_mv[cur ^ 1])[b * HW + p] = mn;
        }
        __syncthreads();

        float recs[4][3];
#pragma unroll 1
        for (int pass = 0; pass < 2; pass++) {
            const float* Sb = g_S + (size_t)((pass * BS + b) * NSTEP + i) * HW * HW;
            const float4* Vs = pass ? Vm : Vp;
            float wgt = pass ? 0.1f : 0.9f;
#pragma unroll 1
            for (int rr = 0; rr < 4; rr++) {
                int q = rg * 32 + w * 4 + rr;
                const float* Srow = Sb + (size_t)q * HW;
                float xs[32];
                float mx = -1e30f;
#pragma unroll
                for (int j = 0; j < 32; j++) {
                    xs[j] = Srow[j * 32 + l];
                    mx = fmaxf(mx, xs[j]);
                }
#pragma unroll
                for (int o = 16; o > 0; o >>= 1)
                    mx = fmaxf(mx, __shfl_xor_sync(0xffffffffu, mx, o));
                float s = 0.f, d0 = 0.f, d1 = 0.f, d2 = 0.f;
#pragma unroll
                for (int j = 0; j < 32; j++) {
                    float e = __expf(xs[j] - mx);
                    float4 vv = Vs[j * 32 + l];
                    s += e;
                    d0 += e * vv.x; d1 += e * vv.y; d2 += e * vv.z;
                }
#pragma unroll
                for (int o = 16; o > 0; o >>= 1) {
                    s += __shfl_xor_sync(0xffffffffu, s, o);
                    d0 += __shfl_xor_sync(0xffffffffu, d0, o);
                    d1 += __shfl_xor_sync(0xffffffffu, d1, o);
                    d2 += __shfl_xor_sync(0xffffffffu, d2, o);
                }
                float inv = wgt / s;
                if (pass == 0) {
                    recs[rr][0] = d0 * inv; recs[rr][1] = d1 * inv; recs[rr][2] = d2 * inv;
                } else {
                    recs[rr][0] += d0 * inv; recs[rr][1] += d1 * inv; recs[rr][2] += d2 * inv;
                }
            }
        }

        if (l == 0) {
            bool mk = g_mask[b * SEQ + i] != 0;
            float* pvn = (float*)g_pv[cur ^ 1] + (size_t)b * HW * 4;
#pragma unroll
            for (int rr = 0; rr < 4; rr++) {
                int q = rg * 32 + w * 4 + rr;
                const float* vp = vin + ((size_t)(b * SEQ + i) * HW + q) * CV;
                float4 o;
                o.x = mk ? vp[0] : recs[rr][0];
                o.y = mk ? vp[1] : recs[rr][1];
                o.z = mk ? vp[2] : recs[rr][2];
                o.w = 0.f;
                ((float4*)pvn)[q] = o;
                float* op = out_v + ((size_t)(b * NSTEP + i) * HW + q) * CV;
                op[0] = recs[rr][0]; op[1] = recs[rr][1]; op[2] = recs[rr][2];
            }
        }
        __threadfence();
        __syncthreads();
        if (t == 0) atomicAdd(&g_chain_done[step], 1);
    }
}

// ---------------- host launcher ----------------------------------------------
extern "C" void kernel_launch(void* const* d_in, const int* in_sizes, int n_in,
                              void* d_out, int out_size) {
    const float* k = (const float*)d_in[0];
    const float* v = (const float*)d_in[1];
    const float* att = (const float*)d_in[2];
    const unsigned char* mask = (const unsigned char*)d_in[3];
    float* out_v = (float*)d_out;
    float* gt = out_v + (size_t)out_size / 2;

    cudaFuncSetAttribute(mega_kernel, cudaFuncAttributeMaxDynamicSharedMemorySize,
                         GSMEM);

    init_kernel<<<BS * HW / 256, 256>>>(v, mask);
    prep_kernel<<<BS * HW * 64 / 256, 256>>>(k, att);
    mega_kernel<<<GRID, 256, GSMEM>>>(v, out_v, gt);
}

// round 16
// speedup vs baseline: 1.2880x; 1.0457x over previous
#include <cuda_runtime.h>
#include <cuda_fp16.h>
#include <cstdint>

#define BS 8
#define SEQ 16
#define HW 1024
#define CK 256
#define CV 3
#define NSTEP 15

#define KTOT 256
#define KC 64
#define NCHUNKS (KTOT / KC) // 4
#define TM 128
#define TN 128
#define STEP_GEMM 1024
#define STEP_CHAIN 256
#define PAIR (STEP_GEMM + STEP_CHAIN)   // 1280
#define GRID (NSTEP * PAIR)             // 19200
#define GSMEM 65536

// ---------------- persistent scratch ----------------------------------------
__device__ __align__(256) __half g_k2[(size_t)BS * SEQ * HW * KTOT];
__device__ __align__(256) __half g_m2[(size_t)BS * NSTEP * HW * KTOT];
__device__ float g_S[(size_t)2 * BS * NSTEP * HW * HW];  // fp32 logits
__device__ float g_sig[BS * SEQ * HW];
__device__ __align__(256) float g_mv[2][BS * HW * 4];
__device__ __align__(256) float g_pv[2][BS * HW * 4];
__device__ int g_mask[BS * SEQ];
__device__ int g_gd[NSTEP][2][BS][8];   // per-(step,pass,b,qt) gemm tile counters
__device__ int g_cd[NSTEP][BS];         // per-(step,b) chain counters

// ---------------- PTX helpers ------------------------------------------------
__device__ __forceinline__ uint32_t s2u(const void* p) {
    uint32_t a;
    asm("{ .reg .u64 t; cvta.to.shared.u64 t, %1; cvt.u32.u64 %0, t; }"
        : "=r"(a) : "l"(p));
    return a;
}
#define SWZ(o) ((o) ^ (((o) >> 3) & 0x70))

__device__ __forceinline__ void cp16(uint32_t dst, const void* src) {
    asm volatile("cp.async.cg.shared.global [%0], [%1], 16;" ::"r"(dst), "l"(src));
}
#define CP_COMMIT() asm volatile("cp.async.commit_group;")

__device__ __forceinline__ void ldsm4(uint32_t& r0, uint32_t& r1, uint32_t& r2,
                                      uint32_t& r3, uint32_t addr) {
    asm volatile("ldmatrix.sync.aligned.m8n8.x4.shared.b16 {%0,%1,%2,%3}, [%4];"
                 : "=r"(r0), "=r"(r1), "=r"(r2), "=r"(r3) : "r"(addr));
}
__device__ __forceinline__ void mma16816(float* d, const uint32_t* a,
                                         const uint32_t* b) {
    asm volatile(
        "mma.sync.aligned.m16n8k16.row.col.f32.f16.f16.f32 "
        "{%0,%1,%2,%3}, {%4,%5,%6,%7}, {%8,%9}, {%0,%1,%2,%3};"
        : "+f"(d[0]), "+f"(d[1]), "+f"(d[2]), "+f"(d[3])
        : "r"(a[0]), "r"(a[1]), "r"(a[2]), "r"(a[3]), "r"(b[0]), "r"(b[1]));
}
__device__ __forceinline__ int ld_acq(const int* p) {
    int v;
    asm volatile("ld.acquire.gpu.b32 %0, [%1];" : "=r"(v) : "l"(p) : "memory");
    return v;
}
__device__ __forceinline__ uint32_t pack_h2(float a, float b) {
    __half2 h = __floats2half2_rn(a, b);
    return *(uint32_t*)&h;
}

// ---------------- init: mask + counters + state ------------------------------
__global__ void init_kernel(const float* __restrict__ v,
                            const unsigned char* __restrict__ m) {
    __shared__ int not_i32;
    int tid = threadIdx.x;
    int t = blockIdx.x * 256 + tid;  // 8192
    if (tid == 0) not_i32 = 0;
    __syncthreads();
    if (blockIdx.x == 0 && tid < 32) {
        int wv = ((const int*)m)[tid];
        if (wv != 0 && wv != 1) not_i32 = 1;
    }
    __syncthreads();
    if (blockIdx.x == 0) {
        if (tid < 128)
            g_mask[tid] = (!not_i32) ? (((const int*)m)[tid] != 0) : (m[tid] != 0);
        int* gd = &g_gd[0][0][0][0];
        for (int e = tid; e < NSTEP * 2 * BS * 8; e += 256) gd[e] = 0;
        int* cd = &g_cd[0][0];
        for (int e = tid; e < NSTEP * BS; e += 256) cd[e] = 0;
    }
    int b = t >> 10, p = t & 1023;
    ((float4*)g_mv[0])[t] = make_float4(0.f, 0.f, 0.f, 0.f);
    const float* vp = v + ((size_t)(b * SEQ) * HW + p) * CV;
    ((float4*)g_pv[0])[t] = make_float4(vp[0], vp[1], vp[2], 0.f);
}

// fused: sigmoid inline + k -> fp16 + m_k recurrence -> fp16; k read once
__global__ void prep_kernel(const float* __restrict__ k,
                            const float* __restrict__ att) {
    int t = blockIdx.x * 256 + threadIdx.x;  // 524288
    int cg = t & 63, p = (t >> 6) & 1023, b = t >> 16;
    float4 m = make_float4(0.f, 0.f, 0.f, 0.f);
#pragma unroll 1
    for (int s = 0; s < SEQ; s++) {
        float4 kv = *(const float4*)(k + ((size_t)(b * SEQ + s) * HW + p) * CK + cg * 4);
        {
            uint2 pk = {pack_h2(kv.x, kv.y), pack_h2(kv.z, kv.w)};
            *(uint2*)(g_k2 + ((size_t)(b * SEQ + s) * HW + p) * KTOT + cg * 4) = pk;
        }
        if (s < NSTEP) {
            float g = 1.f / (1.f + __expf(-att[(b * SEQ + s) * HW + p]));
            if (cg == 0) g_sig[(b * SEQ + s) * HW + p] = g;
            m.x = g * kv.x + (1.f - g) * m.x;
            m.y = g * kv.y + (1.f - g) * m.y;
            m.z = g * kv.z + (1.f - g) * m.z;
            m.w = g * kv.w + (1.f - g) * m.w;
            uint2 pk = {pack_h2(m.x, m.y), pack_h2(m.z, m.w)};
            *(uint2*)(g_m2 + ((size_t)(b * NSTEP + s) * HW + p) * KTOT + cg * 4) = pk;
        }
    }
}

__global__ void gt_copy_kernel(const float* __restrict__ v, float* __restrict__ gt) {
    int e = blockIdx.x * blockDim.x + threadIdx.x;  // 92160 float4
    int b = e / (NSTEP * HW * CV / 4);
    int r = e - b * (NSTEP * HW * CV / 4);
    const float4* src = (const float4*)(v + ((size_t)b * SEQ + 1) * HW * CV);
    float4* dst = (float4*)(gt + (size_t)b * NSTEP * HW * CV);
    dst[r] = src[r];
}

// ---------------- mega kernel: GEMM + chain, delayed bursts, fine deps -------
// bid order: G0 G1 C0 G2 C1 ... G14 C13 C14 (R12 layout, proven).
__global__ __launch_bounds__(256, 2) void mega_kernel(
    const float* __restrict__ vin, float* __restrict__ out_v) {
    extern __shared__ char smem[];
    int r = blockIdx.x;
    int t = threadIdx.x, w = t >> 5, l = t & 31;

    int step, sub;
    bool is_gemm;
    if (r < 2 * STEP_GEMM) {
        is_gemm = true; step = r >> 10; sub = r & 1023;
    } else if (r < 2 * STEP_GEMM + 13 * PAIR) {
        int r2 = r - 2 * STEP_GEMM;
        int pp = r2 / PAIR, q = r2 - pp * PAIR;
        if (q < STEP_CHAIN) { is_gemm = false; step = pp; sub = q; }
        else { is_gemm = true; step = pp + 2; sub = q - STEP_CHAIN; }
    } else {
        int r3 = r - (2 * STEP_GEMM + 13 * PAIR);
        is_gemm = false; step = 13 + (r3 >> 8); sub = r3 & 255;
    }

    if (is_gemm) {
        // ================= GEMM tile =================
        uint32_t sb = s2u(smem);
        int warp_m = w & 3, warp_n = w >> 2;
        int pass = sub >> 9, b = (sub >> 6) & 7, qt = (sub >> 3) & 7, nt = sub & 7;
        int i = step;

        const __half* A = g_k2 + ((size_t)((b * SEQ + i + 1) * HW) + qt * TM) * KTOT;
        const __half* B =
            pass ? g_m2 + ((size_t)((b * NSTEP + i) * HW) + nt * TN) * KTOT
                 : g_k2 + ((size_t)((b * SEQ + i) * HW) + nt * TN) * KTOT;

        auto load_chunk = [&](int ch, int buf) {
            uint32_t abase = sb + buf * 32768;
            uint32_t bbase = abase + 16384;
#pragma unroll
            for (int j = 0; j < 4; j++) {
                int idx = j * 256 + t;
                int row = idx >> 3, k8 = idx & 7;
                uint32_t off = SWZ((uint32_t)(row * 128 + k8 * 16));
                cp16(abase + off, A + (size_t)row * KTOT + ch * KC + k8 * 8);
                cp16(bbase + off, B + (size_t)row * KTOT + ch * KC + k8 * 8);
            }
            CP_COMMIT();
        };

        float acc[2][8][4];
#pragma unroll
        for (int mt = 0; mt < 2; mt++)
#pragma unroll
            for (int n8 = 0; n8 < 8; n8++)
#pragma unroll
                for (int u = 0; u < 4; u++) acc[mt][n8][u] = 0.f;

        load_chunk(0, 0);
        load_chunk(1, 1);

#pragma unroll 1
        for (int c = 0; c < NCHUNKS; c++) {
            if (c < NCHUNKS - 1)
                asm volatile("cp.async.wait_group 1;");
            else
                asm volatile("cp.async.wait_group 0;");
            __syncthreads();

            uint32_t abase = sb + (c & 1) * 32768;
            uint32_t bbase = abase + 16384;
#pragma unroll
            for (int ks = 0; ks < 4; ks++) {
                uint32_t a[2][4];
#pragma unroll
                for (int mt = 0; mt < 2; mt++) {
                    int row = warp_m * 32 + mt * 16 + (l & 15);
                    int kb = ks * 32 + (l >> 4) * 16;
                    ldsm4(a[mt][0], a[mt][1], a[mt][2], a[mt][3],
                          abase + SWZ((uint32_t)(row * 128 + kb)));
                }
                uint32_t bf[4][4];
#pragma unroll
                for (int g16 = 0; g16 < 4; g16++) {
                    int n = warp_n * 64 + g16 * 16 + (l >> 4) * 8 + (l & 7);
                    int kb = ks * 32 + ((l >> 3) & 1) * 16;
                    ldsm4(bf[g16][0], bf[g16][1], bf[g16][2], bf[g16][3],
                          bbase + SWZ((uint32_t)(n * 128 + kb)));
                }
#pragma unroll
                for (int mt = 0; mt < 2; mt++)
#pragma unroll
                    for (int n8 = 0; n8 < 8; n8++) {
                        uint32_t bp[2] = {bf[n8 >> 1][(n8 & 1) * 2],
                                          bf[n8 >> 1][(n8 & 1) * 2 + 1]};
                        mma16816(acc[mt][n8], a[mt], bp);
                    }
            }
            __syncthreads();
            if (c + 2 < NCHUNKS) load_chunk(c + 2, c & 1);
        }

        float* So = g_S + (size_t)((pass * BS + b) * NSTEP + i) * HW * HW +
                    (size_t)(qt * TM) * HW + nt * TN;
#pragma unroll
        for (int mt = 0; mt < 2; mt++)
#pragma unroll
            for (int n8 = 0; n8 < 8; n8++) {
                int r0 = warp_m * 32 + mt * 16 + (l >> 2);
                int c0 = warp_n * 64 + n8 * 8 + (l & 3) * 2;
                *(float2*)(So + (size_t)r0 * HW + c0) =
                    make_float2(acc[mt][n8][0], acc[mt][n8][1]);
                *(float2*)(So + (size_t)(r0 + 8) * HW + c0) =
                    make_float2(acc[mt][n8][2], acc[mt][n8][3]);
            }
        __threadfence();
        __syncthreads();
        if (t == 0) atomicAdd(&g_gd[i][pass][b][qt], 1);
    } else {
        // ================= chain block =================
        int b = sub >> 5, rg = sub & 31;
        int i = step, cur = step & 1;
        int qt = rg >> 2;

        // fine-grained acquire: only the 16 gemm tiles covering our q rows,
        // and only batch b's previous chain blocks.
        if (t == 0) {
            while (ld_acq(&g_gd[i][0][b][qt]) < 8) __nanosleep(128);
            while (ld_acq(&g_gd[i][1][b][qt]) < 8) __nanosleep(128);
            if (i > 0)
                while (ld_acq(&g_cd[i - 1][b]) < 32) __nanosleep(128);
        }
        __syncthreads();

        float4* Vp = (float4*)smem;        // [1024]
        float4* Vm = Vp + HW;              // [1024]
#pragma unroll
        for (int jj = 0; jj < 4; jj++) {
            int p = jj * 256 + t;
            float4 pv = ((const float4*)g_pv[cur])[b * HW + p];
            float4 mo = ((const float4*)g_mv[cur])[b * HW + p];
            float g = g_sig[(b * SEQ + i) * HW + p];
            float4 mn;
            mn.x = g * pv.x + (1.f - g) * mo.x;
            mn.y = g * pv.y + (1.f - g) * mo.y;
            mn.z = g * pv.z + (1.f - g) * mo.z;
            mn.w = 0.f;
            Vp[p] = pv;
            Vm[p] = mn;
            if (rg == 0) ((float4*)g_mv[cur ^ 1])[b * HW + p] = mn;
        }
        __syncthreads();

        float recs[4][3];
#pragma unroll 1
        for (int pass = 0; pass < 2; pass++) {
            const float* Sb = g_S + (size_t)((pass * BS + b) * NSTEP + i) * HW * HW;
            const float4* Vs = pass ? Vm : Vp;
            float wgt = pass ? 0.1f : 0.9f;
#pragma unroll 1
            for (int rr = 0; rr < 4; rr++) {
                int q = rg * 32 + w * 4 + rr;
                const float* Srow = Sb + (size_t)q * HW;
                float xs[32];
                float mx = -1e30f;
#pragma unroll
                for (int j = 0; j < 32; j++) {
                    xs[j] = Srow[j * 32 + l];
                    mx = fmaxf(mx, xs[j]);
                }
#pragma unroll
                for (int o = 16; o > 0; o >>= 1)
                    mx = fmaxf(mx, __shfl_xor_sync(0xffffffffu, mx, o));
                float s = 0.f, d0 = 0.f, d1 = 0.f, d2 = 0.f;
#pragma unroll
                for (int j = 0; j < 32; j++) {
                    float e = __expf(xs[j] - mx);
                    float4 vv = Vs[j * 32 + l];
                    s += e;
                    d0 += e * vv.x; d1 += e * vv.y; d2 += e * vv.z;
                }
#pragma unroll
                for (int o = 16; o > 0; o >>= 1) {
                    s += __shfl_xor_sync(0xffffffffu, s, o);
                    d0 += __shfl_xor_sync(0xffffffffu, d0, o);
                    d1 += __shfl_xor_sync(0xffffffffu, d1, o);
                    d2 += __shfl_xor_sync(0xffffffffu, d2, o);
                }
                float inv = wgt / s;
                if (pass == 0) {
                    recs[rr][0] = d0 * inv; recs[rr][1] = d1 * inv; recs[rr][2] = d2 * inv;
                } else {
                    recs[rr][0] += d0 * inv; recs[rr][1] += d1 * inv; recs[rr][2] += d2 * inv;
                }
            }
        }

        if (l == 0) {
            bool mk = g_mask[b * SEQ + i] != 0;
            float* pvn = (float*)g_pv[cur ^ 1] + (size_t)b * HW * 4;
#pragma unroll
            for (int rr = 0; rr < 4; rr++) {
                int q = rg * 32 + w * 4 + rr;
                const float* vp = vin + ((size_t)(b * SEQ + i) * HW + q) * CV;
                float4 o;
                o.x = mk ? vp[0] : recs[rr][0];
                o.y = mk ? vp[1] : recs[rr][1];
                o.z = mk ? vp[2] : recs[rr][2];
                o.w = 0.f;
                ((float4*)pvn)[q] = o;
                float* op = out_v + ((size_t)(b * NSTEP + i) * HW + q) * CV;
                op[0] = recs[rr][0]; op[1] = recs[rr][1]; op[2] = recs[rr][2];
            }
        }
        __threadfence();
        __syncthreads();
        if (t == 0) atomicAdd(&g_cd[i][b], 1);
    }
}

// ---------------- host launcher ----------------------------------------------
extern "C" void kernel_launch(void* const* d_in, const int* in_sizes, int n_in,
                              void* d_out, int out_size) {
    const float* k = (const float*)d_in[0];
    const float* v = (const float*)d_in[1];
    const float* att = (const float*)d_in[2];
    const unsigned char* mask = (const unsigned char*)d_in[3];
    float* out_v = (float*)d_out;
    float* gt = out_v + (size_t)out_size / 2;

    cudaFuncSetAttribute(mega_kernel, cudaFuncAttributeMaxDynamicSharedMemorySize,
                         GSMEM);

    init_kernel<<<BS * HW / 256, 256>>>(v, mask);
    prep_kernel<<<BS * HW * 64 / 256, 256>>>(k, att);
    mega_kernel<<<GRID, 256, GSMEM>>>(v, out_v);
    gt_copy_kernel<<<360, 256>>>(v, gt);  // independent; fills the drain
}